// round 2
// baseline (speedup 1.0000x reference)
#include <cuda_runtime.h>

// Problem constants
#define HN 4096                 // H = W = 4096
#define RAD 8                   // FIR truncation radius for spline prefilter
#define NTAP (2 * RAD + 1)      // 17 taps

// 64 MB scratch for the 2D spline coefficients (static __device__ -> allowed)
__device__ float g_coef[(size_t)HN * HN];
__device__ double g_num;
__device__ double g_den;

// Inverse cubic B-spline filter h[n] = sqrt(3) * z^|n|, z = sqrt(3)-2.
#define H0 1.7320508075688772f
#define H1 -0.4641016151377546f
#define H2 0.1243556529821417f
#define H3 -0.0333209967908128f
#define H4 0.0089283341810811f
#define H5 -0.0023923399335528f
#define H6 0.0006410991651120f
#define H7 -0.0001717761265249f
#define H8 0.0000460281818343f

__device__ __forceinline__ int mirror_idx(int i) {
    if (i < 0) i = -i;
    if (i >= HN) i = 2 * HN - 2 - i;
    return i;
}

__global__ void init_acc_kernel() {
    g_num = 0.0;
    g_den = 0.0;
}

// ---------------------------------------------------------------------------
// Kernel 1: fused 2D separable 17-tap FIR prefilter (== scipy cubic spline
// prefilter, mirror boundary, truncated at |z|^9 ~ 7e-6).
// Tile 64x64 outputs, halo 8. Register-blocked: 4 outputs/thread/pass,
// LDS.128 window loads, tap weights as FFMA immediates.
// ---------------------------------------------------------------------------
#define TS 64
#define LDW (TS + 2 * RAD)      // 80

__global__ __launch_bounds__(256) void prefilter2d_kernel(const float* __restrict__ in) {
    __shared__ __align__(16) float s_in[LDW][LDW];    // 25.6 KB
    __shared__ __align__(16) float s_mid[LDW][TS];    // 20.5 KB

    const float HK[NTAP] = { H8, H7, H6, H5, H4, H3, H2, H1, H0,
                             H1, H2, H3, H4, H5, H6, H7, H8 };

    const int tx0 = blockIdx.x * TS;
    const int ty0 = blockIdx.y * TS;
    const int tid = threadIdx.x;

    // Stage (64+16)^2 input tile with mirror boundary (coalesced along x)
    for (int idx = tid; idx < LDW * LDW; idx += 256) {
        int r = idx / LDW;
        int c = idx - r * LDW;
        int gr = mirror_idx(ty0 + r - RAD);
        int gc = mirror_idx(tx0 + c - RAD);
        s_in[r][c] = in[gr * HN + gc];
    }
    __syncthreads();

    // Horizontal pass: 80 rows x 64 cols; each thread -> 4 consecutive cols.
    // 1280 items / 256 threads = 5 iterations.
#pragma unroll
    for (int it = 0; it < 5; it++) {
        const int item = it * 256 + tid;
        const int r = item >> 4;            // 0..79
        const int c0 = (item & 15) << 2;    // 0,4,...,60
        const float4* rowp = (const float4*)&s_in[r][c0];
        float acc0 = 0.f, acc1 = 0.f, acc2 = 0.f, acc3 = 0.f;
#pragma unroll
        for (int kv = 0; kv < 5; kv++) {
            float4 v = rowp[kv];
            float vs[4] = { v.x, v.y, v.z, v.w };
#pragma unroll
            for (int s = 0; s < 4; s++) {
                const int k = kv * 4 + s;
                if (k - 0 >= 0 && k - 0 <= 16) acc0 = fmaf(vs[s], HK[k - 0], acc0);
                if (k - 1 >= 0 && k - 1 <= 16) acc1 = fmaf(vs[s], HK[k - 1], acc1);
                if (k - 2 >= 0 && k - 2 <= 16) acc2 = fmaf(vs[s], HK[k - 2], acc2);
                if (k - 3 >= 0 && k - 3 <= 16) acc3 = fmaf(vs[s], HK[k - 3], acc3);
            }
        }
        s_mid[r][c0 + 0] = acc0;
        s_mid[r][c0 + 1] = acc1;
        s_mid[r][c0 + 2] = acc2;
        s_mid[r][c0 + 3] = acc3;
    }
    __syncthreads();

    // Vertical pass: 64x64 outputs; each thread -> 4x4 block. 256 items exactly.
    {
        const int r0 = (tid >> 4) << 2;     // 0,4,...,60
        const int c0 = (tid & 15) << 2;
        float4 acc[4];
#pragma unroll
        for (int j = 0; j < 4; j++) acc[j] = make_float4(0.f, 0.f, 0.f, 0.f);
#pragma unroll
        for (int k = 0; k < 20; k++) {
            float4 m = *(const float4*)&s_mid[r0 + k][c0];
#pragma unroll
            for (int j = 0; j < 4; j++) {
                const int t = k - j;
                if (t >= 0 && t <= 16) {
                    acc[j].x = fmaf(m.x, HK[t], acc[j].x);
                    acc[j].y = fmaf(m.y, HK[t], acc[j].y);
                    acc[j].z = fmaf(m.z, HK[t], acc[j].z);
                    acc[j].w = fmaf(m.w, HK[t], acc[j].w);
                }
            }
        }
#pragma unroll
        for (int j = 0; j < 4; j++) {
            *(float4*)&g_coef[(size_t)(ty0 + r0 + j) * HN + (tx0 + c0)] = acc[j];
        }
    }
}

// ---------------------------------------------------------------------------
// Kernel 2: rotation gather (4x4 cubic taps) + masked-MSE reduction.
// 32x32 output tile/block (block 32x8, 4 rows/thread). Rotated footprint
// (<=38x38, alloc 40x40) staged in SMEM with OOB->0 (== reference's
// where(ok, coef, 0)). Mask denominator analytic: prefilter(ones)==1, so
// r_mask = (sum valid wy) * (sum valid wx).
// ---------------------------------------------------------------------------
#define RGN 40

__global__ __launch_bounds__(256) void rotate_reduce_kernel(const float* __restrict__ fm1) {
    __shared__ float s_c[RGN][RGN];     // 6.4 KB
    __shared__ double s_red[2][8];

    const float cosA = 0.9961946980917455f;   // np.float32(cos(5 deg))
    const float sinA = 0.08715574274765817f;  // np.float32(sin(5 deg))
    const float cc = 2047.5f;                 // (4096-1)/2

    const int x0 = blockIdx.x * 32;
    const int y0 = blockIdx.y * 32;
    const int tid = threadIdx.y * 32 + threadIdx.x;

    // Footprint lower corner (iy monotone +y/-x; ix monotone +y/+x)
    const float iy_min = cosA * ((float)y0 - cc) - sinA * ((float)(x0 + 31) - cc) + cc;
    const float ix_min = sinA * ((float)y0 - cc) + cosA * ((float)x0 - cc) + cc;
    const int ry0 = (int)floorf(iy_min) - 1;
    const int rx0 = (int)floorf(ix_min) - 1;

    // Stage footprint (OOB -> 0)
    for (int idx = tid; idx < RGN * RGN; idx += 256) {
        int r = idx / RGN;
        int c = idx - r * RGN;
        int gy = ry0 + r;
        int gx = rx0 + c;
        float v = 0.0f;
        if ((unsigned)gy < HN && (unsigned)gx < HN) v = g_coef[(size_t)gy * HN + gx];
        s_c[r][c] = v;
    }
    __syncthreads();

    float lnum = 0.0f;
    float lden = 0.0f;
    const int x = x0 + threadIdx.x;
    const float dxv = (float)x - cc;

#pragma unroll
    for (int i = 0; i < 4; i++) {
        const int y = y0 + threadIdx.y + i * 8;
        const float dyv = (float)y - cc;

        const float iy = cosA * dyv - sinA * dxv + cc;
        const float ix = sinA * dyv + cosA * dxv + cc;
        const float byf = floorf(iy);
        const float bxf = floorf(ix);
        const float fy = iy - byf;
        const float fx = ix - bxf;
        const int byi = (int)byf;
        const int bxi = (int)bxf;

        const float fy2 = fy * fy, fy3 = fy2 * fy;
        const float wy0 = (1.0f - 3.0f * fy + 3.0f * fy2 - fy3) * (1.0f / 6.0f);
        const float wy1 = (4.0f - 6.0f * fy2 + 3.0f * fy3) * (1.0f / 6.0f);
        const float wy2 = (1.0f + 3.0f * fy + 3.0f * fy2 - 3.0f * fy3) * (1.0f / 6.0f);
        const float wy3 = fy3 * (1.0f / 6.0f);

        const float fx2 = fx * fx, fx3 = fx2 * fx;
        const float wx0 = (1.0f - 3.0f * fx + 3.0f * fx2 - fx3) * (1.0f / 6.0f);
        const float wx1 = (4.0f - 6.0f * fx2 + 3.0f * fx3) * (1.0f / 6.0f);
        const float wx2 = (1.0f + 3.0f * fx + 3.0f * fx2 - 3.0f * fx3) * (1.0f / 6.0f);
        const float wx3 = fx3 * (1.0f / 6.0f);

        // Analytic rotated mask
        float sy = 0.0f;
        if ((unsigned)(byi - 1) < HN) sy += wy0;
        if ((unsigned)(byi)     < HN) sy += wy1;
        if ((unsigned)(byi + 1) < HN) sy += wy2;
        if ((unsigned)(byi + 2) < HN) sy += wy3;
        float sx = 0.0f;
        if ((unsigned)(bxi - 1) < HN) sx += wx0;
        if ((unsigned)(bxi)     < HN) sx += wx1;
        if ((unsigned)(bxi + 1) < HN) sx += wx2;
        if ((unsigned)(bxi + 2) < HN) sx += wx3;
        lden += sy * sx;

        // 4x4 gather from SMEM (OOB taps already 0)
        const int ly = byi - 1 - ry0;
        const int lx = bxi - 1 - rx0;
        float r0 = s_c[ly + 0][lx] * wx0 + s_c[ly + 0][lx + 1] * wx1
                 + s_c[ly + 0][lx + 2] * wx2 + s_c[ly + 0][lx + 3] * wx3;
        float r1 = s_c[ly + 1][lx] * wx0 + s_c[ly + 1][lx + 1] * wx1
                 + s_c[ly + 1][lx + 2] * wx2 + s_c[ly + 1][lx + 3] * wx3;
        float r2 = s_c[ly + 2][lx] * wx0 + s_c[ly + 2][lx + 1] * wx1
                 + s_c[ly + 2][lx + 2] * wx2 + s_c[ly + 2][lx + 3] * wx3;
        float r3 = s_c[ly + 3][lx] * wx0 + s_c[ly + 3][lx + 1] * wx1
                 + s_c[ly + 3][lx + 2] * wx2 + s_c[ly + 3][lx + 3] * wx3;
        const float val = wy0 * r0 + wy1 * r1 + wy2 * r2 + wy3 * r3;

        const float d = fm1[(size_t)y * HN + x] - val;
        lnum = fmaf(d, d, lnum);
    }

    // Block reduction -> double atomics
#pragma unroll
    for (int o = 16; o; o >>= 1) {
        lnum += __shfl_xor_sync(0xffffffffu, lnum, o);
        lden += __shfl_xor_sync(0xffffffffu, lden, o);
    }
    const int wid = tid >> 5;
    if ((tid & 31) == 0) {
        s_red[0][wid] = (double)lnum;
        s_red[1][wid] = (double)lden;
    }
    __syncthreads();
    if (tid == 0) {
        double n = 0.0, dn = 0.0;
#pragma unroll
        for (int w = 0; w < 8; w++) { n += s_red[0][w]; dn += s_red[1][w]; }
        atomicAdd(&g_num, n);
        atomicAdd(&g_den, dn);
    }
}

__global__ void finalize_kernel(float* __restrict__ out) {
    out[0] = (float)(g_num / g_den);
}

extern "C" void kernel_launch(void* const* d_in, const int* in_sizes, int n_in,
                              void* d_out, int out_size) {
    const float* fm1 = (const float*)d_in[0];
    const float* fm2 = (const float*)d_in[1];
    float* out = (float*)d_out;
    (void)in_sizes; (void)n_in; (void)out_size;

    init_acc_kernel<<<1, 1>>>();

    dim3 g1(HN / TS, HN / TS);                 // 64 x 64 tiles
    prefilter2d_kernel<<<g1, 256>>>(fm2);

    dim3 g2(HN / 32, HN / 32);                 // 128 x 128 tiles
    dim3 b2(32, 8);
    rotate_reduce_kernel<<<g2, b2>>>(fm1);

    finalize_kernel<<<1, 1>>>(out);
}

// round 3
// speedup vs baseline: 1.0319x; 1.0319x over previous
#include <cuda_runtime.h>

// Problem constants
#define HN 4096                 // H = W = 4096
#define RAD 5                   // FIR truncation radius for spline prefilter
#define NTAP (2 * RAD + 1)      // 11 taps

// 64 MB scratch for the 2D spline coefficients (static __device__ -> allowed)
__device__ float g_coef[(size_t)HN * HN];
__device__ double g_num;
__device__ double g_den;
__device__ unsigned g_ticket = 0;

// Inverse cubic B-spline filter h[n] = sqrt(3) * z^|n|, z = sqrt(3)-2.
#define H0f 1.7320508075688772f
#define H1f -0.4641016151377546f
#define H2f 0.1243556529821417f
#define H3f -0.0333209967908128f
#define H4f 0.0089283341810811f
#define H5f -0.0023923399335528f

__device__ __forceinline__ int mirror_idx(int i) {
    if (i < 0) i = -i;
    if (i >= HN) i = 2 * HN - 2 - i;
    return i;
}

// ---------------------------------------------------------------------------
// Kernel 1: fused 2D separable 11-tap FIR prefilter (== scipy cubic spline
// prefilter, mirror boundary, truncated at |z|^6 ~ 2.4e-4; loss-level error
// ~1e-5 by measured sensitivity). Tile 64x64, halo 5.
// Horizontal: 8 outputs/thread via 5x LDS.128 window. Vertical: 4x4/thread.
// Tap weights are compile-time constants -> FFMA with immediate (rt=1).
// ---------------------------------------------------------------------------
#define TS 64
#define LDW (TS + 2 * RAD)      // 74
#define SW 76                    // padded stage width (16B-aligned rows)

__global__ __launch_bounds__(256) void prefilter2d_kernel(const float* __restrict__ in) {
    __shared__ __align__(16) float s_in[LDW][SW];    // 22.5 KB
    __shared__ __align__(16) float s_mid[LDW][TS];   // 18.9 KB

    const float HK[NTAP] = { H5f, H4f, H3f, H2f, H1f, H0f,
                             H1f, H2f, H3f, H4f, H5f };

    const int tx0 = blockIdx.x * TS;
    const int ty0 = blockIdx.y * TS;
    const int tid = threadIdx.x;

    // Zero global accumulators once per grid (rotate kernel runs after us)
    if (blockIdx.x == 0 && blockIdx.y == 0 && tid == 0) {
        g_num = 0.0;
        g_den = 0.0;
    }

    // Stage 74x76 input tile with mirror boundary (coalesced along x)
    for (int idx = tid; idx < LDW * SW; idx += 256) {
        int r = idx / SW;
        int c = idx - r * SW;
        s_in[r][c] = in[(size_t)mirror_idx(ty0 + r - RAD) * HN + mirror_idx(tx0 + c - RAD)];
    }
    __syncthreads();

    // Horizontal pass: 74 rows x 64 cols; 8 consecutive outputs per thread.
    // items = 74 * 8 = 592 -> 3 guarded iterations.
#pragma unroll
    for (int it = 0; it < 3; it++) {
        const int item = it * 256 + tid;
        if (item < LDW * 8) {
            const int r = item >> 3;
            const int cg = (item & 7) << 3;          // 0,8,...,56
            float v[20];
#pragma unroll
            for (int m = 0; m < 5; m++) {
                float4 t = *(const float4*)&s_in[r][cg + 4 * m];
                v[4 * m + 0] = t.x; v[4 * m + 1] = t.y;
                v[4 * m + 2] = t.z; v[4 * m + 3] = t.w;
            }
            float a[8];
#pragma unroll
            for (int j = 0; j < 8; j++) a[j] = 0.0f;
#pragma unroll
            for (int m = 0; m < 18; m++) {
#pragma unroll
                for (int j = 0; j < 8; j++) {
                    const int k = m - j;
                    if (k >= 0 && k < NTAP) a[j] = fmaf(v[m], HK[k], a[j]);
                }
            }
            *(float4*)&s_mid[r][cg]     = make_float4(a[0], a[1], a[2], a[3]);
            *(float4*)&s_mid[r][cg + 4] = make_float4(a[4], a[5], a[6], a[7]);
        }
    }
    __syncthreads();

    // Vertical pass: 64x64 outputs; each thread a 4x4 block (256 items exactly)
    {
        const int r0 = (tid >> 4) << 2;     // 0,4,...,60
        const int c0 = (tid & 15) << 2;
        float4 acc[4];
#pragma unroll
        for (int j = 0; j < 4; j++) acc[j] = make_float4(0.f, 0.f, 0.f, 0.f);
#pragma unroll
        for (int k = 0; k < 14; k++) {
            float4 m4 = *(const float4*)&s_mid[r0 + k][c0];
#pragma unroll
            for (int j = 0; j < 4; j++) {
                const int t = k - j;
                if (t >= 0 && t < NTAP) {
                    acc[j].x = fmaf(m4.x, HK[t], acc[j].x);
                    acc[j].y = fmaf(m4.y, HK[t], acc[j].y);
                    acc[j].z = fmaf(m4.z, HK[t], acc[j].z);
                    acc[j].w = fmaf(m4.w, HK[t], acc[j].w);
                }
            }
        }
#pragma unroll
        for (int j = 0; j < 4; j++) {
            *(float4*)&g_coef[(size_t)(ty0 + r0 + j) * HN + (tx0 + c0)] = acc[j];
        }
    }
}

// ---------------------------------------------------------------------------
// Kernel 2: rotation gather (4x4 cubic taps) + masked-MSE reduction + fused
// last-block finalize. 32x32 output tile/block (32x8 threads, 4 rows each).
// Rotated footprint (<=38x38, alloc 40x40) staged in SMEM with OOB->0
// (== reference's where(ok, coef, 0)). Mask denominator analytic:
// prefilter(ones)==1, so r_mask = (sum valid wy)*(sum valid wx).
// ---------------------------------------------------------------------------
#define RGN 40
#define NBLK ((HN / 32) * (HN / 32))    // 16384

__global__ __launch_bounds__(256) void rotate_reduce_kernel(const float* __restrict__ fm1,
                                                            float* __restrict__ out) {
    __shared__ float s_c[RGN][RGN];     // 6.4 KB
    __shared__ double s_red[2][8];

    const float cosA = 0.9961946980917455f;   // np.float32(cos(5 deg))
    const float sinA = 0.08715574274765817f;  // np.float32(sin(5 deg))
    const float cc = 2047.5f;                 // (4096-1)/2

    const int x0 = blockIdx.x * 32;
    const int y0 = blockIdx.y * 32;
    const int tid = threadIdx.y * 32 + threadIdx.x;

    // Footprint lower corner (iy monotone +y/-x; ix monotone +y/+x)
    const float iy_min = cosA * ((float)y0 - cc) - sinA * ((float)(x0 + 31) - cc) + cc;
    const float ix_min = sinA * ((float)y0 - cc) + cosA * ((float)x0 - cc) + cc;
    const int ry0 = (int)floorf(iy_min) - 1;
    const int rx0 = (int)floorf(ix_min) - 1;

    // Stage footprint (OOB -> 0)
    for (int idx = tid; idx < RGN * RGN; idx += 256) {
        int r = idx / RGN;
        int c = idx - r * RGN;
        int gy = ry0 + r;
        int gx = rx0 + c;
        float v = 0.0f;
        if ((unsigned)gy < HN && (unsigned)gx < HN) v = g_coef[(size_t)gy * HN + gx];
        s_c[r][c] = v;
    }
    __syncthreads();

    float lnum = 0.0f;
    float lden = 0.0f;
    const int x = x0 + threadIdx.x;
    const float dxv = (float)x - cc;

#pragma unroll
    for (int i = 0; i < 4; i++) {
        const int y = y0 + threadIdx.y + i * 8;
        const float dyv = (float)y - cc;

        const float iy = cosA * dyv - sinA * dxv + cc;
        const float ix = sinA * dyv + cosA * dxv + cc;
        const float byf = floorf(iy);
        const float bxf = floorf(ix);
        const float fy = iy - byf;
        const float fx = ix - bxf;
        const int byi = (int)byf;
        const int bxi = (int)bxf;

        const float fy2 = fy * fy, fy3 = fy2 * fy;
        const float wy0 = (1.0f - 3.0f * fy + 3.0f * fy2 - fy3) * (1.0f / 6.0f);
        const float wy1 = (4.0f - 6.0f * fy2 + 3.0f * fy3) * (1.0f / 6.0f);
        const float wy2 = (1.0f + 3.0f * fy + 3.0f * fy2 - 3.0f * fy3) * (1.0f / 6.0f);
        const float wy3 = fy3 * (1.0f / 6.0f);

        const float fx2 = fx * fx, fx3 = fx2 * fx;
        const float wx0 = (1.0f - 3.0f * fx + 3.0f * fx2 - fx3) * (1.0f / 6.0f);
        const float wx1 = (4.0f - 6.0f * fx2 + 3.0f * fx3) * (1.0f / 6.0f);
        const float wx2 = (1.0f + 3.0f * fx + 3.0f * fx2 - 3.0f * fx3) * (1.0f / 6.0f);
        const float wx3 = fx3 * (1.0f / 6.0f);

        // Analytic rotated mask
        float sy = 0.0f;
        if ((unsigned)(byi - 1) < HN) sy += wy0;
        if ((unsigned)(byi)     < HN) sy += wy1;
        if ((unsigned)(byi + 1) < HN) sy += wy2;
        if ((unsigned)(byi + 2) < HN) sy += wy3;
        float sx = 0.0f;
        if ((unsigned)(bxi - 1) < HN) sx += wx0;
        if ((unsigned)(bxi)     < HN) sx += wx1;
        if ((unsigned)(bxi + 1) < HN) sx += wx2;
        if ((unsigned)(bxi + 2) < HN) sx += wx3;
        lden += sy * sx;

        // 4x4 gather from SMEM (OOB taps already 0)
        const int ly = byi - 1 - ry0;
        const int lx = bxi - 1 - rx0;
        float r0 = s_c[ly + 0][lx] * wx0 + s_c[ly + 0][lx + 1] * wx1
                 + s_c[ly + 0][lx + 2] * wx2 + s_c[ly + 0][lx + 3] * wx3;
        float r1 = s_c[ly + 1][lx] * wx0 + s_c[ly + 1][lx + 1] * wx1
                 + s_c[ly + 1][lx + 2] * wx2 + s_c[ly + 1][lx + 3] * wx3;
        float r2 = s_c[ly + 2][lx] * wx0 + s_c[ly + 2][lx + 1] * wx1
                 + s_c[ly + 2][lx + 2] * wx2 + s_c[ly + 2][lx + 3] * wx3;
        float r3 = s_c[ly + 3][lx] * wx0 + s_c[ly + 3][lx + 1] * wx1
                 + s_c[ly + 3][lx + 2] * wx2 + s_c[ly + 3][lx + 3] * wx3;
        const float val = wy0 * r0 + wy1 * r1 + wy2 * r2 + wy3 * r3;

        const float d = fm1[(size_t)y * HN + x] - val;
        lnum = fmaf(d, d, lnum);
    }

    // Block reduction -> double atomics
#pragma unroll
    for (int o = 16; o; o >>= 1) {
        lnum += __shfl_xor_sync(0xffffffffu, lnum, o);
        lden += __shfl_xor_sync(0xffffffffu, lden, o);
    }
    const int wid = tid >> 5;
    if ((tid & 31) == 0) {
        s_red[0][wid] = (double)lnum;
        s_red[1][wid] = (double)lden;
    }
    __syncthreads();
    if (tid == 0) {
        double n = 0.0, dn = 0.0;
#pragma unroll
        for (int w = 0; w < 8; w++) { n += s_red[0][w]; dn += s_red[1][w]; }
        atomicAdd(&g_num, n);
        atomicAdd(&g_den, dn);

        // Fused finalize: last block to arrive computes the quotient.
        __threadfence();
        unsigned t = atomicAdd(&g_ticket, 1u);
        if (t == NBLK - 1u) {
            double fn = *(volatile double*)&g_num;
            double fd = *(volatile double*)&g_den;
            out[0] = (float)(fn / fd);
            g_ticket = 0u;          // reset for next graph replay
        }
    }
}

extern "C" void kernel_launch(void* const* d_in, const int* in_sizes, int n_in,
                              void* d_out, int out_size) {
    const float* fm1 = (const float*)d_in[0];
    const float* fm2 = (const float*)d_in[1];
    float* out = (float*)d_out;
    (void)in_sizes; (void)n_in; (void)out_size;

    dim3 g1(HN / TS, HN / TS);                 // 64 x 64 tiles
    prefilter2d_kernel<<<g1, 256>>>(fm2);

    dim3 g2(HN / 32, HN / 32);                 // 128 x 128 tiles
    dim3 b2(32, 8);
    rotate_reduce_kernel<<<g2, b2>>>(fm1, out);
}

// round 4
// speedup vs baseline: 1.1827x; 1.1461x over previous
#include <cuda_runtime.h>

// Problem constants
#define HN 4096                 // H = W = 4096
#define RAD 5                   // FIR truncation radius for spline prefilter
#define NTAP (2 * RAD + 1)      // 11 taps

// 64 MB scratch for the 2D spline coefficients (static __device__ -> allowed)
__device__ float g_coef[(size_t)HN * HN];
__device__ double g_num;
__device__ double g_den;
__device__ unsigned g_ticket = 0;

// Inverse cubic B-spline filter h[n] = sqrt(3) * z^|n|, z = sqrt(3)-2.
#define H0f 1.7320508075688772f
#define H1f -0.4641016151377546f
#define H2f 0.1243556529821417f
#define H3f -0.0333209967908128f
#define H4f 0.0089283341810811f
#define H5f -0.0023923399335528f

__device__ __forceinline__ int mirror_idx(int i) {
    if (i < 0) i = -i;
    if (i >= HN) i = 2 * HN - 2 - i;
    return i;
}

// ---------------------------------------------------------------------------
// Kernel 1: fused 2D separable 11-tap FIR prefilter (== scipy cubic spline
// prefilter, mirror boundary, truncated at |z|^6 ~ 2.4e-4; loss-level error
// ~5e-7 measured). Tile 64x64, halo 5.
// ---------------------------------------------------------------------------
#define TS 64
#define LDW (TS + 2 * RAD)      // 74
#define SW 76                    // padded stage width (16B-aligned rows)

__global__ __launch_bounds__(256) void prefilter2d_kernel(const float* __restrict__ in) {
    __shared__ __align__(16) float s_in[LDW][SW];    // 22.5 KB
    __shared__ __align__(16) float s_mid[LDW][TS];   // 18.9 KB

    const float HK[NTAP] = { H5f, H4f, H3f, H2f, H1f, H0f,
                             H1f, H2f, H3f, H4f, H5f };

    const int tx0 = blockIdx.x * TS;
    const int ty0 = blockIdx.y * TS;
    const int tid = threadIdx.x;

    // Zero global accumulators once per grid (rotate kernel runs after us)
    if (blockIdx.x == 0 && blockIdx.y == 0 && tid == 0) {
        g_num = 0.0;
        g_den = 0.0;
    }

    // Stage 74x76 input tile with mirror boundary (coalesced along x)
    for (int idx = tid; idx < LDW * SW; idx += 256) {
        int r = idx / SW;
        int c = idx - r * SW;
        s_in[r][c] = in[(size_t)mirror_idx(ty0 + r - RAD) * HN + mirror_idx(tx0 + c - RAD)];
    }
    __syncthreads();

    // Horizontal pass: 74 rows x 64 cols; 8 consecutive outputs per thread.
#pragma unroll
    for (int it = 0; it < 3; it++) {
        const int item = it * 256 + tid;
        if (item < LDW * 8) {
            const int r = item >> 3;
            const int cg = (item & 7) << 3;          // 0,8,...,56
            float v[20];
#pragma unroll
            for (int m = 0; m < 5; m++) {
                float4 t = *(const float4*)&s_in[r][cg + 4 * m];
                v[4 * m + 0] = t.x; v[4 * m + 1] = t.y;
                v[4 * m + 2] = t.z; v[4 * m + 3] = t.w;
            }
            float a[8];
#pragma unroll
            for (int j = 0; j < 8; j++) a[j] = 0.0f;
#pragma unroll
            for (int m = 0; m < 18; m++) {
#pragma unroll
                for (int j = 0; j < 8; j++) {
                    const int k = m - j;
                    if (k >= 0 && k < NTAP) a[j] = fmaf(v[m], HK[k], a[j]);
                }
            }
            *(float4*)&s_mid[r][cg]     = make_float4(a[0], a[1], a[2], a[3]);
            *(float4*)&s_mid[r][cg + 4] = make_float4(a[4], a[5], a[6], a[7]);
        }
    }
    __syncthreads();

    // Vertical pass: 64x64 outputs; each thread a 4x4 block (256 items exactly)
    {
        const int r0 = (tid >> 4) << 2;     // 0,4,...,60
        const int c0 = (tid & 15) << 2;
        float4 acc[4];
#pragma unroll
        for (int j = 0; j < 4; j++) acc[j] = make_float4(0.f, 0.f, 0.f, 0.f);
#pragma unroll
        for (int k = 0; k < 14; k++) {
            float4 m4 = *(const float4*)&s_mid[r0 + k][c0];
#pragma unroll
            for (int j = 0; j < 4; j++) {
                const int t = k - j;
                if (t >= 0 && t < NTAP) {
                    acc[j].x = fmaf(m4.x, HK[t], acc[j].x);
                    acc[j].y = fmaf(m4.y, HK[t], acc[j].y);
                    acc[j].z = fmaf(m4.z, HK[t], acc[j].z);
                    acc[j].w = fmaf(m4.w, HK[t], acc[j].w);
                }
            }
        }
#pragma unroll
        for (int j = 0; j < 4; j++) {
            *(float4*)&g_coef[(size_t)(ty0 + r0 + j) * HN + (tx0 + c0)] = acc[j];
        }
    }
}

// ---------------------------------------------------------------------------
// Kernel 2: rotation gather (4x4 cubic taps) + masked-MSE reduction + fused
// last-block finalize. 32x32 output tile/block (32x8 threads, 4 rows each).
// Rotated footprint (<=38x38) staged in SMEM with ROW STRIDE 65 so that
// bank(ly,lx) = (ly+lx) mod 32 -> the warp's diagonal tap pattern is
// conflict-free (was ~3-way at stride 40). OOB cells -> 0 (== reference's
// where(ok, coef, 0)). Interior blocks skip the mask predicates entirely:
// prefilter(ones)==1 and sum(wy)*sum(wx)==1 (+-3e-7), so den += 1 per pixel.
// ---------------------------------------------------------------------------
#define RGN 40
#define SCW 65
#define NBLK ((HN / 32) * (HN / 32))    // 16384

__global__ __launch_bounds__(256) void rotate_reduce_kernel(const float* __restrict__ fm1,
                                                            float* __restrict__ out) {
    __shared__ float s_c[RGN * SCW];    // 10.4 KB
    __shared__ double s_red[2][8];

    const float cosA = 0.9961946980917455f;   // np.float32(cos(5 deg))
    const float sinA = 0.08715574274765817f;  // np.float32(sin(5 deg))
    const float cc = 2047.5f;                 // (4096-1)/2

    const int x0 = blockIdx.x * 32;
    const int y0 = blockIdx.y * 32;
    const int tid = threadIdx.y * 32 + threadIdx.x;

    // Footprint lower corner (iy monotone +y/-x; ix monotone +y/+x)
    const float iy_min = cosA * ((float)y0 - cc) - sinA * ((float)(x0 + 31) - cc) + cc;
    const float ix_min = sinA * ((float)y0 - cc) + cosA * ((float)x0 - cc) + cc;
    const int ry0 = (int)floorf(iy_min) - 1;
    const int rx0 = (int)floorf(ix_min) - 1;

    // Whole staged footprint in-bounds -> no mask work needed per pixel
    const bool interior = (ry0 >= 0) & (rx0 >= 0) &
                          (ry0 + RGN <= HN) & (rx0 + RGN <= HN);

    // Stage footprint (OOB -> 0)
    for (int idx = tid; idx < RGN * RGN; idx += 256) {
        int r = idx / RGN;
        int c = idx - r * RGN;
        int gy = ry0 + r;
        int gx = rx0 + c;
        float v = 0.0f;
        if ((unsigned)gy < HN && (unsigned)gx < HN) v = g_coef[(size_t)gy * HN + gx];
        s_c[r * SCW + c] = v;
    }
    __syncthreads();

    float lnum = 0.0f;
    float lden = 0.0f;
    const int x = x0 + threadIdx.x;
    const float dxv = (float)x - cc;
    const float ix = sinA * 0.0f + cosA * dxv + cc - cosA * cc + cc * 0.0f; // placeholder avoided below

#pragma unroll
    for (int i = 0; i < 4; i++) {
        const int y = y0 + threadIdx.y + i * 8;
        const float dyv = (float)y - cc;

        const float iyv = cosA * dyv - sinA * dxv + cc;
        const float ixv = sinA * dyv + cosA * dxv + cc;
        const float byf = floorf(iyv);
        const float bxf = floorf(ixv);
        const float fy = iyv - byf;
        const float fx = ixv - bxf;
        const int byi = (int)byf;
        const int bxi = (int)bxf;

        // Horner-form cubic B-spline weights
        const float fy2 = fy * fy, fy3 = fy2 * fy;
        const float wy0 = fmaf(fy, fmaf(fy, fmaf(fy, -(1.f/6.f), 0.5f), -0.5f), (1.f/6.f));
        const float wy1 = fmaf(fy2, fmaf(fy, 0.5f, -1.0f), (2.f/3.f));
        const float wy2 = fmaf(fy, fmaf(fy, fmaf(fy, -0.5f, 0.5f), 0.5f), (1.f/6.f));
        const float wy3 = fy3 * (1.f/6.f);

        const float fx2 = fx * fx, fx3 = fx2 * fx;
        const float wx0 = fmaf(fx, fmaf(fx, fmaf(fx, -(1.f/6.f), 0.5f), -0.5f), (1.f/6.f));
        const float wx1 = fmaf(fx2, fmaf(fx, 0.5f, -1.0f), (2.f/3.f));
        const float wx2 = fmaf(fx, fmaf(fx, fmaf(fx, -0.5f, 0.5f), 0.5f), (1.f/6.f));
        const float wx3 = fx3 * (1.f/6.f);

        if (interior) {
            lden += 1.0f;                           // sum(wy)*sum(wx) == 1 (+-3e-7)
        } else {
            float sy = 0.0f;
            if ((unsigned)(byi - 1) < HN) sy += wy0;
            if ((unsigned)(byi)     < HN) sy += wy1;
            if ((unsigned)(byi + 1) < HN) sy += wy2;
            if ((unsigned)(byi + 2) < HN) sy += wy3;
            float sx = 0.0f;
            if ((unsigned)(bxi - 1) < HN) sx += wx0;
            if ((unsigned)(bxi)     < HN) sx += wx1;
            if ((unsigned)(bxi + 1) < HN) sx += wx2;
            if ((unsigned)(bxi + 2) < HN) sx += wx3;
            lden += sy * sx;
        }

        // 4x4 gather from SMEM (OOB taps already 0); row offsets fold into
        // LDS immediate offsets off a single base pointer.
        const int ly = byi - 1 - ry0;
        const int lx = bxi - 1 - rx0;
        const float* p = s_c + (ly * SCW + lx);
        float r0 = (p[0]       * wx0 + p[1]       * wx1) + (p[2]       * wx2 + p[3]       * wx3);
        float r1 = (p[SCW]     * wx0 + p[SCW + 1] * wx1) + (p[SCW + 2] * wx2 + p[SCW + 3] * wx3);
        float r2 = (p[2*SCW]   * wx0 + p[2*SCW+1] * wx1) + (p[2*SCW+2] * wx2 + p[2*SCW+3] * wx3);
        float r3 = (p[3*SCW]   * wx0 + p[3*SCW+1] * wx1) + (p[3*SCW+2] * wx2 + p[3*SCW+3] * wx3);
        const float val = (wy0 * r0 + wy1 * r1) + (wy2 * r2 + wy3 * r3);

        const float d = fm1[(size_t)y * HN + x] - val;
        lnum = fmaf(d, d, lnum);
    }

    // Block reduction -> double atomics
#pragma unroll
    for (int o = 16; o; o >>= 1) {
        lnum += __shfl_xor_sync(0xffffffffu, lnum, o);
        lden += __shfl_xor_sync(0xffffffffu, lden, o);
    }
    const int wid = tid >> 5;
    if ((tid & 31) == 0) {
        s_red[0][wid] = (double)lnum;
        s_red[1][wid] = (double)lden;
    }
    __syncthreads();
    if (tid == 0) {
        double n = 0.0, dn = 0.0;
#pragma unroll
        for (int w = 0; w < 8; w++) { n += s_red[0][w]; dn += s_red[1][w]; }
        atomicAdd(&g_num, n);
        atomicAdd(&g_den, dn);

        // Fused finalize: last block to arrive computes the quotient.
        __threadfence();
        unsigned t = atomicAdd(&g_ticket, 1u);
        if (t == NBLK - 1u) {
            double fn = *(volatile double*)&g_num;
            double fd = *(volatile double*)&g_den;
            out[0] = (float)(fn / fd);
            g_ticket = 0u;          // reset for next graph replay
        }
    }
}

extern "C" void kernel_launch(void* const* d_in, const int* in_sizes, int n_in,
                              void* d_out, int out_size) {
    const float* fm1 = (const float*)d_in[0];
    const float* fm2 = (const float*)d_in[1];
    float* out = (float*)d_out;
    (void)in_sizes; (void)n_in; (void)out_size;

    dim3 g1(HN / TS, HN / TS);                 // 64 x 64 tiles
    prefilter2d_kernel<<<g1, 256>>>(fm2);

    dim3 g2(HN / 32, HN / 32);                 // 128 x 128 tiles
    dim3 b2(32, 8);
    rotate_reduce_kernel<<<g2, b2>>>(fm1, out);
}

// round 5
// speedup vs baseline: 1.2409x; 1.0492x over previous
#include <cuda_runtime.h>
#include <cstdint>

// Problem constants
#define HN 4096                 // H = W = 4096
#define RAD 5                   // FIR truncation radius for spline prefilter
#define NTAP (2 * RAD + 1)      // 11 taps

// 64 MB scratch for the 2D spline coefficients (static __device__ -> allowed)
__device__ float g_coef[(size_t)HN * HN];
__device__ double g_num;
__device__ double g_den;
__device__ unsigned g_ticket = 0;

// Inverse cubic B-spline filter h[n] = sqrt(3) * z^|n|, z = sqrt(3)-2.
#define H0f 1.7320508075688772f
#define H1f -0.4641016151377546f
#define H2f 0.1243556529821417f
#define H3f -0.0333209967908128f
#define H4f 0.0089283341810811f
#define H5f -0.0023923399335528f

// packed f32x2 helpers
#define PK_MUL(out, a, b) asm("mul.rn.f32x2 %0, %1, %2;" : "=l"(out) : "l"(a), "l"(b))
#define PK_FMA(out, a, b, c) asm("fma.rn.f32x2 %0, %1, %2, %3;" : "=l"(out) : "l"(a), "l"(b), "l"(c))
#define PK_PACK(out, lo, hi) asm("mov.b64 %0, {%1, %2};" : "=l"(out) : "f"(lo), "f"(hi))
#define PK_UNPACK(lo, hi, in) asm("mov.b64 {%0, %1}, %2;" : "=f"(lo), "=f"(hi) : "l"(in))

__device__ __forceinline__ int mirror_idx(int i) {
    if (i < 0) i = -i;
    if (i >= HN) i = 2 * HN - 2 - i;
    return i;
}

// ---------------------------------------------------------------------------
// Kernel 1: fused 2D separable 11-tap FIR prefilter (== scipy cubic spline
// prefilter, mirror boundary, truncated at |z|^6 ~ 2.4e-4; loss-level error
// ~4e-7 measured). Tile 64x64, halo 5.
// ---------------------------------------------------------------------------
#define TS 64
#define LDW (TS + 2 * RAD)      // 74
#define SW 76                    // padded stage width

__global__ __launch_bounds__(256) void prefilter2d_kernel(const float* __restrict__ in) {
    __shared__ __align__(16) float s_in[LDW][SW];    // 22.5 KB
    __shared__ __align__(16) float s_mid[LDW][TS];   // 18.9 KB

    const float HK[NTAP] = { H5f, H4f, H3f, H2f, H1f, H0f,
                             H1f, H2f, H3f, H4f, H5f };

    const int tx0 = blockIdx.x * TS;
    const int ty0 = blockIdx.y * TS;
    const int tid = threadIdx.x;

    // Zero global accumulators once per grid (rotate kernel runs after us)
    if (blockIdx.x == 0 && blockIdx.y == 0 && tid == 0) {
        g_num = 0.0;
        g_den = 0.0;
    }

    // Stage 74x76 input tile (mirror only needed on the boundary ring)
    const bool pin = (tx0 >= RAD) && (ty0 >= RAD) &&
                     (tx0 + TS + RAD <= HN) && (ty0 + TS + RAD <= HN);
    if (pin) {
        const float* base = in + (size_t)(ty0 - RAD) * HN + (tx0 - RAD);
        for (int idx = tid; idx < LDW * SW; idx += 256) {
            int r = idx / SW;
            int c = idx - r * SW;
            s_in[r][c] = base[(size_t)r * HN + c];
        }
    } else {
        for (int idx = tid; idx < LDW * SW; idx += 256) {
            int r = idx / SW;
            int c = idx - r * SW;
            s_in[r][c] = in[(size_t)mirror_idx(ty0 + r - RAD) * HN + mirror_idx(tx0 + c - RAD)];
        }
    }
    __syncthreads();

    // Horizontal pass: 74 rows x 64 cols; 8 consecutive outputs per thread.
#pragma unroll
    for (int it = 0; it < 3; it++) {
        const int item = it * 256 + tid;
        if (item < LDW * 8) {
            const int r = item >> 3;
            const int cg = (item & 7) << 3;          // 0,8,...,56
            float v[20];
#pragma unroll
            for (int m = 0; m < 5; m++) {
                float4 t = *(const float4*)&s_in[r][cg + 4 * m];
                v[4 * m + 0] = t.x; v[4 * m + 1] = t.y;
                v[4 * m + 2] = t.z; v[4 * m + 3] = t.w;
            }
            float a[8];
#pragma unroll
            for (int j = 0; j < 8; j++) a[j] = 0.0f;
#pragma unroll
            for (int m = 0; m < 18; m++) {
#pragma unroll
                for (int j = 0; j < 8; j++) {
                    const int k = m - j;
                    if (k >= 0 && k < NTAP) a[j] = fmaf(v[m], HK[k], a[j]);
                }
            }
            *(float4*)&s_mid[r][cg]     = make_float4(a[0], a[1], a[2], a[3]);
            *(float4*)&s_mid[r][cg + 4] = make_float4(a[4], a[5], a[6], a[7]);
        }
    }
    __syncthreads();

    // Vertical pass: 64x64 outputs; each thread a 4x4 block (256 items exactly)
    {
        const int r0 = (tid >> 4) << 2;     // 0,4,...,60
        const int c0 = (tid & 15) << 2;
        float4 acc[4];
#pragma unroll
        for (int j = 0; j < 4; j++) acc[j] = make_float4(0.f, 0.f, 0.f, 0.f);
#pragma unroll
        for (int k = 0; k < 14; k++) {
            float4 m4 = *(const float4*)&s_mid[r0 + k][c0];
#pragma unroll
            for (int j = 0; j < 4; j++) {
                const int t = k - j;
                if (t >= 0 && t < NTAP) {
                    acc[j].x = fmaf(m4.x, HK[t], acc[j].x);
                    acc[j].y = fmaf(m4.y, HK[t], acc[j].y);
                    acc[j].z = fmaf(m4.z, HK[t], acc[j].z);
                    acc[j].w = fmaf(m4.w, HK[t], acc[j].w);
                }
            }
        }
#pragma unroll
        for (int j = 0; j < 4; j++) {
            *(float4*)&g_coef[(size_t)(ty0 + r0 + j) * HN + (tx0 + c0)] = acc[j];
        }
    }
}

// ---------------------------------------------------------------------------
// Kernel 2: rotation gather (4x4 cubic taps) + masked-MSE reduction + fused
// last-block finalize. 32x32 output tile/block. Footprint staged at ROW
// STRIDE 64 -> bank = lx mod 32 (ly irrelevant): conflict-free gather and
// shift-based indexing. Weights evaluated in packed f32x2 ((fx,fy) pair).
// Interior blocks: mask denominator is exactly 1/px (prefilter(ones)==1,
// sum(w)==1), added as a single 1024.0 per block.
// ---------------------------------------------------------------------------
#define RGN 40
#define SCW 64
#define NBLK ((HN / 32) * (HN / 32))    // 16384

template<bool INTERIOR>
__device__ __forceinline__ void rotate_loop(
    const float* __restrict__ fm1, const float* __restrict__ s_c,
    int x, int y_base, int ry0, int rx0,
    float& lnum, float& lden)
{
    const float cosA = 0.9961946980917455f;
    const float sinA = 0.08715574274765817f;
    const float cc = 2047.5f;

    const float dxv = (float)x - cc;
    const float t1 = fmaf(-sinA, dxv, cc);   // iy = cosA*dyv + t1
    const float t2 = fmaf(cosA, dxv, cc);    // ix = sinA*dyv + t2

    // packed constants (lo and hi identical)
    uint64_t Cm16, Ch, Cmh, C16, Cm1, C23;
    PK_PACK(Cm16, -(1.f/6.f), -(1.f/6.f));
    PK_PACK(Ch, 0.5f, 0.5f);
    PK_PACK(Cmh, -0.5f, -0.5f);
    PK_PACK(C16, (1.f/6.f), (1.f/6.f));
    PK_PACK(Cm1, -1.0f, -1.0f);
    PK_PACK(C23, (2.f/3.f), (2.f/3.f));

    float dyv = (float)y_base - cc;

#pragma unroll
    for (int i = 0; i < 4; i++) {
        const float iyv = fmaf(cosA, dyv, t1);
        const float ixv = fmaf(sinA, dyv, t2);
        const float byf = floorf(iyv);
        const float bxf = floorf(ixv);
        const float fy = iyv - byf;
        const float fx = ixv - bxf;
        const int byi = (int)byf;
        const int bxi = (int)bxf;

        // packed weight evaluation: lo lane = x-weights, hi lane = y-weights
        uint64_t f, f2, f3, t, u, v, w0p, w1p, w2p, w3p;
        PK_PACK(f, fx, fy);
        PK_MUL(f2, f, f);
        PK_MUL(f3, f2, f);
        PK_FMA(t, f, Cm16, Ch);
        PK_FMA(t, f, t, Cmh);
        PK_FMA(w0p, f, t, C16);
        PK_FMA(u, f, Ch, Cm1);
        PK_FMA(w1p, f2, u, C23);
        PK_FMA(v, f, Cmh, Ch);
        PK_FMA(v, f, v, Ch);
        PK_FMA(w2p, f, v, C16);
        PK_MUL(w3p, f3, C16);

        float wx0, wy0, wx1, wy1, wx2, wy2, wx3, wy3;
        PK_UNPACK(wx0, wy0, w0p);
        PK_UNPACK(wx1, wy1, w1p);
        PK_UNPACK(wx2, wy2, w2p);
        PK_UNPACK(wx3, wy3, w3p);

        if (!INTERIOR) {
            float sy = 0.0f;
            if ((unsigned)(byi - 1) < HN) sy += wy0;
            if ((unsigned)(byi)     < HN) sy += wy1;
            if ((unsigned)(byi + 1) < HN) sy += wy2;
            if ((unsigned)(byi + 2) < HN) sy += wy3;
            float sx = 0.0f;
            if ((unsigned)(bxi - 1) < HN) sx += wx0;
            if ((unsigned)(bxi)     < HN) sx += wx1;
            if ((unsigned)(bxi + 1) < HN) sx += wx2;
            if ((unsigned)(bxi + 2) < HN) sx += wx3;
            lden += sy * sx;
        }

        // 4x4 gather (row stride 64 -> shift indexing, conflict-free banks)
        const int ly = byi - 1 - ry0;
        const int lx = bxi - 1 - rx0;
        const float* p = s_c + (ly << 6) + lx;
        float r0 = (p[0*SCW]   * wx0 + p[0*SCW+1] * wx1) + (p[0*SCW+2] * wx2 + p[0*SCW+3] * wx3);
        float r1 = (p[1*SCW]   * wx0 + p[1*SCW+1] * wx1) + (p[1*SCW+2] * wx2 + p[1*SCW+3] * wx3);
        float r2 = (p[2*SCW]   * wx0 + p[2*SCW+1] * wx1) + (p[2*SCW+2] * wx2 + p[2*SCW+3] * wx3);
        float r3 = (p[3*SCW]   * wx0 + p[3*SCW+1] * wx1) + (p[3*SCW+2] * wx2 + p[3*SCW+3] * wx3);
        const float val = (wy0 * r0 + wy1 * r1) + (wy2 * r2 + wy3 * r3);

        const int y = y_base + i * 8;
        const float d = fm1[(size_t)y * HN + x] - val;
        lnum = fmaf(d, d, lnum);

        dyv += 8.0f;    // exact
    }
}

__global__ __launch_bounds__(256) void rotate_reduce_kernel(const float* __restrict__ fm1,
                                                            float* __restrict__ out) {
    __shared__ float s_c[RGN * SCW];    // 10.24 KB
    __shared__ double s_red[2][8];

    const float cosA = 0.9961946980917455f;
    const float sinA = 0.08715574274765817f;
    const float cc = 2047.5f;

    const int x0 = blockIdx.x * 32;
    const int y0 = blockIdx.y * 32;
    const int tid = threadIdx.y * 32 + threadIdx.x;

    // Footprint lower corner (iy monotone +y/-x; ix monotone +y/+x)
    const float iy_min = cosA * ((float)y0 - cc) - sinA * ((float)(x0 + 31) - cc) + cc;
    const float ix_min = sinA * ((float)y0 - cc) + cosA * ((float)x0 - cc) + cc;
    const int ry0 = (int)floorf(iy_min) - 1;
    const int rx0 = (int)floorf(ix_min) - 1;

    const bool interior = (ry0 >= 0) & (rx0 >= 0) &
                          (ry0 + RGN <= HN) & (rx0 + RGN <= HN);

    // Stage 40x40 footprint at stride 64 (OOB -> 0)
    if (interior) {
        const float* base = g_coef + (size_t)ry0 * HN + rx0;
        for (int idx = tid; idx < RGN * RGN; idx += 256) {
            int r = idx / RGN;
            int c = idx - r * RGN;
            s_c[(r << 6) + c] = base[(size_t)r * HN + c];
        }
    } else {
        for (int idx = tid; idx < RGN * RGN; idx += 256) {
            int r = idx / RGN;
            int c = idx - r * RGN;
            int gy = ry0 + r;
            int gx = rx0 + c;
            float v = 0.0f;
            if ((unsigned)gy < HN && (unsigned)gx < HN) v = g_coef[(size_t)gy * HN + gx];
            s_c[(r << 6) + c] = v;
        }
    }
    __syncthreads();

    float lnum = 0.0f;
    float lden = 0.0f;
    const int x = x0 + threadIdx.x;
    const int y_base = y0 + threadIdx.y;

    if (interior) {
        rotate_loop<true>(fm1, s_c, x, y_base, ry0, rx0, lnum, lden);
    } else {
        rotate_loop<false>(fm1, s_c, x, y_base, ry0, rx0, lnum, lden);
    }

    // Block reduction -> double atomics
#pragma unroll
    for (int o = 16; o; o >>= 1) {
        lnum += __shfl_xor_sync(0xffffffffu, lnum, o);
        if (!interior) lden += __shfl_xor_sync(0xffffffffu, lden, o);
    }
    const int wid = tid >> 5;
    if ((tid & 31) == 0) {
        s_red[0][wid] = (double)lnum;
        s_red[1][wid] = (double)lden;
    }
    __syncthreads();
    if (tid == 0) {
        double n = 0.0, dn = 0.0;
#pragma unroll
        for (int w = 0; w < 8; w++) { n += s_red[0][w]; dn += s_red[1][w]; }
        if (interior) dn = 1024.0;          // exact: 32x32 pixels, mask==1 each
        atomicAdd(&g_num, n);
        atomicAdd(&g_den, dn);

        // Fused finalize: last block to arrive computes the quotient.
        __threadfence();
        unsigned t = atomicAdd(&g_ticket, 1u);
        if (t == NBLK - 1u) {
            double fn = *(volatile double*)&g_num;
            double fd = *(volatile double*)&g_den;
            out[0] = (float)(fn / fd);
            g_ticket = 0u;          // reset for next graph replay
        }
    }
}

extern "C" void kernel_launch(void* const* d_in, const int* in_sizes, int n_in,
                              void* d_out, int out_size) {
    const float* fm1 = (const float*)d_in[0];
    const float* fm2 = (const float*)d_in[1];
    float* out = (float*)d_out;
    (void)in_sizes; (void)n_in; (void)out_size;

    dim3 g1(HN / TS, HN / TS);                 // 64 x 64 tiles
    prefilter2d_kernel<<<g1, 256>>>(fm2);

    dim3 g2(HN / 32, HN / 32);                 // 128 x 128 tiles
    dim3 b2(32, 8);
    rotate_reduce_kernel<<<g2, b2>>>(fm1, out);
}